// round 16
// baseline (speedup 1.0000x reference)
#include <cuda_runtime.h>
#include <cuda_fp16.h>
#include <cstdint>

#define GS 128
#define OBS 1024
#define HH 256
#define OUTD 1024
#define NO 18
#define BB 256
#define M_ROWS (BB * GS)   // 32768

// ---------------- scratch (device globals: no allocation allowed) -------------
__device__ __half g_Yh16[(size_t)M_ROWS * 256];  // rel half of Y, fp16
__device__ __half g_Yr16[(size_t)M_ROWS * 256];  // root half of Y, fp16
__device__ __half g_rh16[BB * 512];              // [r1 | h0_n] per batch, fp16
__device__ float g_no[BB * OUTD];                // node_out per batch
__device__ __half g_Xf[(size_t)M_ROWS * OBS];    // gathered X, fp16
__device__ __half g_Wf[512 * 1024];              // Wt[n][k] fp16 (layer 0)
__device__ __half g_W1f[512 * 1024];             // W1 concat [k][n] fp16 (layer 1)

// ---------------- helpers -----------------------------------------------------
__device__ __forceinline__ unsigned su32(const void* p) {
    return (unsigned)__cvta_generic_to_shared(p);
}
__device__ __forceinline__ unsigned pckh(float a, float b) {
    return (unsigned)__half_as_ushort(__float2half_rn(a))
         | ((unsigned)__half_as_ushort(__float2half_rn(b)) << 16);
}
#define STS8(addr, v) \
    asm volatile("st.shared.v2.u32 [%0], {%1, %2};" :: "r"(addr), "r"((v).x), "r"((v).y))
#define CPASYNC16(saddr, gptr) \
    asm volatile("cp.async.cg.shared.global [%0], [%1], 16;" \
                 :: "r"(saddr), "l"(gptr))
#define CPCOMMIT() asm volatile("cp.async.commit_group;")
#define CPWAIT1()  asm volatile("cp.async.wait_group 1;")
#define CPWAIT0()  asm volatile("cp.async.wait_group 0;")
#define LDSM4(r0, r1, r2, r3, a) \
    asm volatile("ldmatrix.sync.aligned.m8n8.x4.shared.b16 {%0,%1,%2,%3}, [%4];" \
                 : "=r"(r0), "=r"(r1), "=r"(r2), "=r"(r3) : "r"(a))
#define LDSM4T(r0, r1, r2, r3, a) \
    asm volatile("ldmatrix.sync.aligned.m8n8.x4.trans.shared.b16 {%0,%1,%2,%3}, [%4];" \
                 : "=r"(r0), "=r"(r1), "=r"(r2), "=r"(r3) : "r"(a))

__device__ __forceinline__ void mma_f16(float* c, const unsigned* a, const unsigned* b) {
    asm volatile(
        "mma.sync.aligned.m16n8k16.row.col.f32.f16.f16.f32 "
        "{%0,%1,%2,%3}, {%4,%5,%6,%7}, {%8,%9}, {%0,%1,%2,%3};"
        : "+f"(c[0]), "+f"(c[1]), "+f"(c[2]), "+f"(c[3])
        : "r"(a[0]), "r"(a[1]), "r"(a[2]), "r"(a[3]), "r"(b[0]), "r"(b[1]));
}

// ---------------- kernel 0: gather X rows + fp16 convert ----------------------
__global__ __launch_bounds__(256) void k_xsplit(const float* __restrict__ flat,
                                                const float* __restrict__ nodes,
                                                const int* __restrict__ num_nodes)
{
    int gid = blockIdx.x * 256 + threadIdx.x;
    int row = gid >> 6;
    int c0 = (gid & 63) * 16;
    int b = row >> 7, j = row & 127;
    const float* src = (j == num_nodes[b]) ? (flat + (size_t)b * OBS)
                                           : (nodes + (size_t)row * OBS);
    __half* dh = g_Xf + (size_t)row * OBS + c0;
#pragma unroll
    for (int i = 0; i < 4; ++i) {
        float4 v = *(const float4*)(src + c0 + i * 4);
        *(uint2*)(dh + i * 4) = make_uint2(pckh(v.x, v.y), pckh(v.z, v.w));
    }
}

// ---------------- kernel 0b: transpose + fp16 convert of [W0_rel|W0_root] -----
__global__ void k_wsplit(const float* __restrict__ W0_rel,
                         const float* __restrict__ W0_root)
{
    __shared__ float tile[32][33];
    int kb = blockIdx.x * 32, nb = blockIdx.y * 32;
    int tx = threadIdx.x, ty = threadIdx.y;  // (32, 8)
#pragma unroll
    for (int j = 0; j < 32; j += 8) {
        int k = kb + ty + j, n = nb + tx;
        float v = (n < 256) ? W0_rel[(size_t)k * 256 + n]
                            : W0_root[(size_t)k * 256 + (n - 256)];
        tile[ty + j][tx] = v;
    }
    __syncthreads();
#pragma unroll
    for (int j = 0; j < 32; j += 8) {
        int n = nb + ty + j, k = kb + tx;
        g_Wf[(size_t)n * 1024 + k] = __float2half_rn(tile[tx][ty + j]);
    }
}

// ---------------- kernel 0c: fp16 convert of W1 concat [k][n] -----------------
__global__ __launch_bounds__(256) void k_w1split(const float* __restrict__ W1_rel,
                                                 const float* __restrict__ W1_root)
{
    int gid = blockIdx.x * 256 + threadIdx.x;   // 8 halves each
    int k = gid >> 7;                           // 0..511
    int n = (gid & 127) * 8;
    const float* src = (k < 256) ? (W1_rel + (size_t)k * 1024 + n)
                                 : (W1_root + (size_t)(k - 256) * 1024 + n);
    float4 v0 = *(const float4*)(src);
    float4 v1 = *(const float4*)(src + 4);
    *(uint4*)(g_W1f + (size_t)k * 1024 + n) =
        make_uint4(pckh(v0.x, v0.y), pckh(v0.z, v0.w),
                   pckh(v1.x, v1.y), pckh(v1.z, v1.w));
}

// ---------------- kernel 1: Y = Xf @ Wf^T, cp.async 3-stage, 1 sync/chunk -----
#define STAGE_BYTES 32768
#define SMEM_DYN (3 * STAGE_BYTES)     // 98304 -> 2 CTAs/SM (192K)

__global__ __launch_bounds__(256, 2) void k_gemm0_mma()
{
    extern __shared__ char dynsmem[];
    unsigned sm = su32(dynsmem);
    int tid = threadIdx.x, lane = tid & 31, wid = tid >> 5;
    int wm = wid >> 2, wn = wid & 3;               // warp tile: 64m x 32n
    int m0 = blockIdx.y * 128, n0 = blockIdx.x * 128;

    int cb = tid & 7;
    int r_lo = tid >> 3;
    unsigned swo = (unsigned)((cb ^ (r_lo & 7)) << 4);

    int l7 = lane & 7;
    unsigned a_row = (unsigned)(wm * 64 + (lane & 15)) * 128;
    unsigned a_cbx = (unsigned)(lane >> 4);
    unsigned b_row = (unsigned)(wn * 32 + l7) * 128;
    unsigned b_cbx = (unsigned)((lane >> 3) & 1);
    unsigned b_nt4 = (unsigned)((lane >> 4) & 1) * 1024;

    float acc[4][4][4];
#pragma unroll
    for (int mt = 0; mt < 4; ++mt)
#pragma unroll
        for (int nt = 0; nt < 4; ++nt)
#pragma unroll
            for (int r = 0; r < 4; ++r) acc[mt][nt][r] = 0.f;

#define ISSUE(cc)                                                              \
    {                                                                          \
        unsigned sb = sm + ((cc) % 3) * STAGE_BYTES;                           \
        int kt = (cc) * 64;                                                    \
        _Pragma("unroll")                                                      \
        for (int i = 0; i < 4; ++i) {                                          \
            int r = i * 32 + r_lo;                                             \
            unsigned so = (unsigned)(r * 128) + swo;                           \
            size_t goA = (size_t)(m0 + r) * 1024 + kt + cb * 8;                \
            size_t goB = (size_t)(n0 + r) * 1024 + kt + cb * 8;                \
            CPASYNC16(sb + so,         g_Xf + goA);                            \
            CPASYNC16(sb + 16384 + so, g_Wf + goB);                            \
        }                                                                      \
        CPCOMMIT();                                                            \
    }

    ISSUE(0);
    ISSUE(1);

    for (int c = 0; c < 16; ++c) {
        if (c + 1 < 16) { CPWAIT1(); }   // stage c resident (≤1 group pending)
        else            { CPWAIT0(); }
        __syncthreads();                 // all warps done reading stage c-1
        if (c + 2 < 16) ISSUE(c + 2);    // writes stage (c-1)%3 — now safe
        unsigned base = sm + (c % 3) * STAGE_BYTES;
#pragma unroll
        for (int s = 0; s < 4; ++s) {
            unsigned a[4][4], bf[2][4];
            unsigned asw = (unsigned)((((unsigned)(s * 2) + a_cbx) ^ (unsigned)l7) << 4);
            unsigned bsw = (unsigned)((((unsigned)(s * 2) + b_cbx) ^ (unsigned)l7) << 4);
#pragma unroll
            for (int mt = 0; mt < 4; ++mt) {
                unsigned aaddr = base + a_row + mt * 2048 + asw;
                LDSM4(a[mt][0], a[mt][1], a[mt][2], a[mt][3], aaddr);
            }
#pragma unroll
            for (int p = 0; p < 2; ++p) {
                unsigned baddr = base + 16384 + b_row + p * 2048 + b_nt4 + bsw;
                LDSM4(bf[p][0], bf[p][1], bf[p][2], bf[p][3], baddr);
            }
#pragma unroll
            for (int mt = 0; mt < 4; ++mt)
#pragma unroll
                for (int p = 0; p < 2; ++p) {
                    mma_f16(acc[mt][p * 2 + 0], a[mt], bf[p] + 0);
                    mma_f16(acc[mt][p * 2 + 1], a[mt], bf[p] + 2);
                }
        }
    }

    // epilogue: both halves stored fp16 (rel -> g_Yh16, root -> g_Yr16)
    bool isrel = (n0 < 256);
#pragma unroll
    for (int mt = 0; mt < 4; ++mt) {
        int m = m0 + wm * 64 + mt * 16 + (lane >> 2);
#pragma unroll
        for (int nt = 0; nt < 4; ++nt) {
            int n = n0 + wn * 32 + nt * 8 + (lane & 3) * 2;
            __half* dst0 = isrel ? (g_Yh16 + (size_t)m * 256 + n)
                                 : (g_Yr16 + (size_t)m * 256 + (n - 256));
            __half* dst1 = isrel ? (g_Yh16 + (size_t)(m + 8) * 256 + n)
                                 : (g_Yr16 + (size_t)(m + 8) * 256 + (n - 256));
            *(unsigned*)dst0 = pckh(acc[mt][nt][0], acc[mt][nt][1]);
            *(unsigned*)dst1 = pckh(acc[mt][nt][2], acc[mt][nt][3]);
        }
    }
#undef ISSUE
}

// ---------------- kernel 2: one CTA per batch, fused h0 + masked reduce -------
// smem: At 32K | Yh0 32K | Yh1 32K | bitw 2K | red 2K | sn
#define AT_OFF   0
#define YH0_OFF  32768
#define YH1_OFF  65536
#define BITW_OFF 98304
#define RED_OFF  100352
#define SN_OFF   102400
#define H0_SMEM  102416

__global__ __launch_bounds__(256, 2) void k_h0row_mma(const int* __restrict__ adj,
                                                      const int* __restrict__ num_nodes,
                                                      const float* __restrict__ b0)
{
    extern __shared__ char dynsmem[];
    unsigned sm = su32(dynsmem);
    unsigned At = sm + AT_OFF;
    unsigned YhBuf[2] = {sm + YH0_OFF, sm + YH1_OFF};
    unsigned* bitw = (unsigned*)(dynsmem + BITW_OFF);   // [128][4]
    float* red = (float*)(dynsmem + RED_OFF);           // [4][128]
    int* snp = (int*)(dynsmem + SN_OFF);
    int tid = threadIdx.x, lane = tid & 31, wid = tid >> 5;
    int wm = wid >> 1, wn = wid & 1;       // warp tile: 32 rows x 64 cols
    int b = blockIdx.x;

    // ---- prefetch both Yrel ch-tiles via cp.async ----
#pragma unroll
    for (int ch = 0; ch < 2; ++ch) {
#pragma unroll
        for (int it = 0; it < 8; ++it) {
            int s = it * 256 + tid;
            int j = s >> 4, g = s & 15;
            unsigned so = (unsigned)(j * 256 + ((g ^ (j & 7)) << 4));
            CPASYNC16(YhBuf[ch] + so,
                      g_Yh16 + (size_t)(b * 128 + j) * 256 + ch * 128 + g * 8);
        }
        CPCOMMIT();
    }

    // ---- adjacency bitset via ballot, MLP-8 batched loads ----
    const int* adjb = adj + (size_t)b * GS * GS;
#pragma unroll
    for (int g8 = 0; g8 < 8; ++g8) {
        int va[8];
#pragma unroll
        for (int it = 0; it < 8; ++it)
            va[it] = adjb[g8 * 2048 + it * 256 + tid];
#pragma unroll
        for (int it = 0; it < 8; ++it) {
            int idx = g8 * 2048 + it * 256 + tid;
            unsigned m = __ballot_sync(0xffffffffu, va[it] != 0);
            if ((tid & 31) == 0) bitw[(idx >> 7) * 4 + ((idx & 127) >> 5)] = m;
        }
    }
    __syncthreads();
    if (tid == 0) {
        int n = num_nodes[b];
        *snp = n;
        bitw[n * 4 + (n >> 5)] |= 1u << (n & 31);
        if (n > 0) {
            bitw[n * 4 + ((n - 1) >> 5)] |= 1u << ((n - 1) & 31);
            bitw[(n - 1) * 4 + (n >> 5)] |= 1u << (n & 31);
        }
    }
    __syncthreads();

    // ---- expand A^T[i][j] into fp16 0/1, swizzled ----
#pragma unroll
    for (int it = 0; it < 16; ++it) {
        int s = it * 256 + tid;
        int i = s >> 5, j0 = (s & 31) * 4;
        unsigned w = (unsigned)(i >> 5), bi = (unsigned)(i & 31);
        const unsigned ONE = 0x3C00u;
        unsigned e0 = (bitw[(j0 + 0) * 4 + w] >> bi) & 1u;
        unsigned e1 = (bitw[(j0 + 1) * 4 + w] >> bi) & 1u;
        unsigned e2 = (bitw[(j0 + 2) * 4 + w] >> bi) & 1u;
        unsigned e3 = (bitw[(j0 + 3) * 4 + w] >> bi) & 1u;
        unsigned p0 = (e0 * ONE) | ((e1 * ONE) << 16);
        unsigned p1 = (e2 * ONE) | ((e3 * ONE) << 16);
        unsigned so = (unsigned)(i * 256 + (((j0 >> 3) ^ (i & 7)) << 4) + (j0 & 7) * 2);
        STS8(At + so, make_uint2(p0, p1));
    }

    int n = *snp;
    unsigned nw = (unsigned)(n >> 5), nbit = 1u << (n & 31);

#pragma unroll
    for (int ch = 0; ch < 2; ++ch) {
        if (ch == 0) CPWAIT1(); else CPWAIT0();
        __syncthreads();
        unsigned Yh = YhBuf[ch];

        float acc[2][8][4];
#pragma unroll
        for (int mt = 0; mt < 2; ++mt)
#pragma unroll
            for (int nt = 0; nt < 8; ++nt)
#pragma unroll
                for (int r = 0; r < 4; ++r) acc[mt][nt][r] = 0.f;

        for (int s = 0; s < 8; ++s) {
            unsigned af[2][4];
#pragma unroll
            for (int mt = 0; mt < 2; ++mt) {
                int r = wm * 32 + mt * 16 + (lane & 15);
                unsigned ad = At + (unsigned)(r * 256)
                            + ((((unsigned)(s * 2 + (lane >> 4))) ^ (unsigned)(r & 7)) << 4);
                LDSM4(af[mt][0], af[mt][1], af[mt][2], af[mt][3], ad);
            }
            int jj = s * 16 + (lane & 15);
            unsigned brow = (unsigned)(jj * 256);
            unsigned jx = (unsigned)(jj & 7);
#pragma unroll
            for (int ntp = 0; ntp < 4; ++ntp) {
                unsigned colblk = (unsigned)(wn * 8 + ntp * 2) + (unsigned)(lane >> 4);
                unsigned bd = brow + ((colblk ^ jx) << 4);
                unsigned bfr[4];
                LDSM4T(bfr[0], bfr[1], bfr[2], bfr[3], Yh + bd);
#pragma unroll
                for (int mt = 0; mt < 2; ++mt) {
                    mma_f16(acc[mt][ntp * 2 + 0], af[mt], bfr + 0);
                    mma_f16(acc[mt][ntp * 2 + 1], af[mt], bfr + 2);
                }
            }
        }

        // ---- epilogue: relu(+root(fp16)+bias), masked r1, h0_n -> fp16 ----
        float r1p[8][2];
#pragma unroll
        for (int nt = 0; nt < 8; ++nt) { r1p[nt][0] = 0.f; r1p[nt][1] = 0.f; }

#pragma unroll
        for (int mt = 0; mt < 2; ++mt)
#pragma unroll
            for (int hr = 0; hr < 2; ++hr) {
                int i = wm * 32 + mt * 16 + (lane >> 2) + hr * 8;
                bool msk = (bitw[i * 4 + nw] & nbit) != 0;
                const __half* rootrow = g_Yr16 + (size_t)(b * 128 + i) * 256 + ch * 128;
#pragma unroll
                for (int nt = 0; nt < 8; ++nt) {
                    int cl = wn * 64 + nt * 8 + (lane & 3) * 2;
                    float2 root = __half22float2(*(const __half2*)(rootrow + cl));
                    float2 bbv = *(const float2*)(b0 + ch * 128 + cl);
                    float o0 = fmaxf(acc[mt][nt][hr * 2 + 0] + root.x + bbv.x, 0.f);
                    float o1 = fmaxf(acc[mt][nt][hr * 2 + 1] + root.y + bbv.y, 0.f);
                    if (msk) { r1p[nt][0] += o0; r1p[nt][1] += o1; }
                    if (i == n)
                        *(unsigned*)(g_rh16 + b * 512 + 256 + ch * 128 + cl) =
                            pckh(o0, o1);
                }
            }

#pragma unroll
        for (int nt = 0; nt < 8; ++nt)
#pragma unroll
            for (int t = 0; t < 2; ++t) {
                float v = r1p[nt][t];
                v += __shfl_xor_sync(0xffffffffu, v, 4);
                v += __shfl_xor_sync(0xffffffffu, v, 8);
                v += __shfl_xor_sync(0xffffffffu, v, 16);
                r1p[nt][t] = v;
            }
        if ((lane >> 2) == 0) {
#pragma unroll
            for (int nt = 0; nt < 8; ++nt) {
                red[wm * 128 + wn * 64 + nt * 8 + (lane & 3) * 2 + 0] = r1p[nt][0];
                red[wm * 128 + wn * 64 + nt * 8 + (lane & 3) * 2 + 1] = r1p[nt][1];
            }
        }
        __syncthreads();
        if (tid < 128) {
            float ssum = red[tid] + red[128 + tid] + red[256 + tid] + red[384 + tid];
            g_rh16[b * 512 + ch * 128 + tid] = __float2half_rn(ssum);
        }
        __syncthreads();
    }
}

// ---------------- kernel 4: node_out = relu(rh16 @ W1f + b1) via fp16 mma -----
#define G1_SMEM 65536

__global__ __launch_bounds__(256, 2) void k_gemm1_mma(const float* __restrict__ b1)
{
    extern __shared__ char dynsmem[];
    unsigned sm = su32(dynsmem);
    unsigned Ab0 = sm, Ab1 = sm + 16384;
    unsigned Bb0 = sm + 32768, Bb1 = sm + 49152;
    int tid = threadIdx.x, lane = tid & 31, wid = tid >> 5;
    int wm = wid >> 2, wn = wid & 3;               // warp tile: 64m x 32n
    int m0 = blockIdx.y * 128, n0 = blockIdx.x * 128;

    int cbA = tid & 7, rA_lo = tid >> 3;
    unsigned swoA = (unsigned)((cbA ^ (rA_lo & 7)) << 4);
    int gB = tid & 15, rB_lo = tid >> 4;

    int l7 = lane & 7;
    unsigned a_row = (unsigned)(wm * 64 + (lane & 15)) * 128;
    unsigned a_cbx = (unsigned)(lane >> 4);

    float acc[4][4][4];
#pragma unroll
    for (int mt = 0; mt < 4; ++mt)
#pragma unroll
        for (int nt = 0; nt < 4; ++nt)
#pragma unroll
            for (int r = 0; r < 4; ++r) acc[mt][nt][r] = 0.f;

#define ISSUE1(cc)                                                             \
    {                                                                          \
        unsigned Ab = ((cc) & 1) ? Ab1 : Ab0;                                  \
        unsigned Bb = ((cc) & 1) ? Bb1 : Bb0;                                  \
        int kt = (cc) * 64;                                                    \
        _Pragma("unroll")                                                      \
        for (int i = 0; i < 4; ++i) {                                          \
            int rA = i * 32 + rA_lo;                                           \
            CPASYNC16(Ab + (unsigned)(rA * 128) + swoA,                        \
                      g_rh16 + (size_t)(m0 + rA) * 512 + kt + cbA * 8);        \
            int rB = i * 16 + rB_lo;                                           \
            unsigned soB = (unsigned)(rB * 256 + ((gB ^ (rB & 7)) << 4));      \
            CPASYNC16(Bb + soB,                                                \
                      g_W1f + (size_t)(kt + rB) * 1024 + n0 + gB * 8);         \
        }                                                                      \
        CPCOMMIT();                                                            \
    }

    ISSUE1(0);

    for (int c = 0; c < 8; ++c) {
        if (c + 1 < 8) { ISSUE1(c + 1); CPWAIT1(); }
        else           { CPWAIT0(); }
        __syncthreads();
        unsigned Ab = (c & 1) ? Ab1 : Ab0;
        unsigned Bb = (c & 1) ? Bb1 : Bb0;
#pragma unroll
        for (int s = 0; s < 4; ++s) {
            unsigned a[4][4];
            unsigned asw = (unsigned)((((unsigned)(s * 2) + a_cbx) ^ (unsigned)l7) << 4);
#pragma unroll
            for (int mt = 0; mt < 4; ++mt)
                LDSM4(a[mt][0], a[mt][1], a[mt][2], a[mt][3],
                      Ab + a_row + mt * 2048 + asw);
            int jj = s * 16 + (lane & 15);
            unsigned brow = (unsigned)(jj * 256);
            unsigned jx = (unsigned)(jj & 7);
#pragma unroll
            for (int ntp = 0; ntp < 2; ++ntp) {
                unsigned colblk = (unsigned)(wn * 4 + ntp * 2) + (unsigned)(lane >> 4);
                unsigned bd = brow + ((colblk ^ jx) << 4);
                unsigned bfr[4];
                LDSM4T(bfr[0], bfr[1], bfr[2], bfr[3], Bb + bd);
#pragma unroll
                for (int mt = 0; mt < 4; ++mt) {
                    mma_f16(acc[mt][ntp * 2 + 0], a[mt], bfr + 0);
                    mma_f16(acc[mt][ntp * 2 + 1], a[mt], bfr + 2);
                }
            }
        }
        __syncthreads();
    }

    // epilogue: +b1, relu -> g_no fp32
#pragma unroll
    for (int mt = 0; mt < 4; ++mt) {
        int m = m0 + wm * 64 + mt * 16 + (lane >> 2);
#pragma unroll
        for (int nt = 0; nt < 4; ++nt) {
            int n = n0 + wn * 32 + nt * 8 + (lane & 3) * 2;
            float2 bb = *(const float2*)(b1 + n);
            *(float2*)(g_no + (size_t)m * 1024 + n) =
                make_float2(fmaxf(acc[mt][nt][0] + bb.x, 0.f),
                            fmaxf(acc[mt][nt][1] + bb.y, 0.f));
            *(float2*)(g_no + (size_t)(m + 8) * 1024 + n) =
                make_float2(fmaxf(acc[mt][nt][2] + bb.x, 0.f),
                            fmaxf(acc[mt][nt][3] + bb.y, 0.f));
        }
    }
#undef ISSUE1
}

// ---------------- kernel 5: logits + value -----------------------------------
__global__ __launch_bounds__(256) void k_out(const float* __restrict__ Wl,
                                             const float* __restrict__ bl,
                                             const float* __restrict__ Wv,
                                             const float* __restrict__ bv,
                                             float* __restrict__ out, int out_size)
{
    int b = blockIdx.x;
    int w = threadIdx.x >> 5, lane = threadIdx.x & 31;
    const float* nb = g_no + (size_t)b * 1024;
    for (int o = w; o < 19; o += 8) {
        float acc = 0.f;
        if (o < 18) {
            for (int i = lane; i < 1024; i += 32) acc += nb[i] * Wl[i * 18 + o];
        } else {
            for (int i = lane; i < 1024; i += 32) acc += nb[i] * Wv[i];
        }
#pragma unroll
        for (int s = 16; s; s >>= 1) acc += __shfl_down_sync(0xffffffffu, acc, s);
        if (lane == 0) {
            if (o < 18) {
                int idx = b * NO + o;
                if (idx < out_size) out[idx] = acc + bl[o];
            } else {
                int idx = BB * NO + b;
                if (idx < out_size) out[idx] = acc + bv[0];
            }
        }
    }
}

// ---------------- launch ------------------------------------------------------
extern "C" void kernel_launch(void* const* d_in, const int* in_sizes, int n_in,
                              void* d_out, int out_size)
{
    const float* flat      = (const float*)d_in[0];
    const float* nodes     = (const float*)d_in[1];
    const int*   num_nodes = (const int*)d_in[2];
    const int*   adj       = (const int*)d_in[3];
    // d_in[4] = seq_lens (unused)
    const float* W0_rel  = (const float*)d_in[5];
    const float* b0      = (const float*)d_in[6];
    const float* W0_root = (const float*)d_in[7];
    const float* W1_rel  = (const float*)d_in[8];
    const float* b1      = (const float*)d_in[9];
    const float* W1_root = (const float*)d_in[10];
    const float* Wl      = (const float*)d_in[11];
    const float* bl      = (const float*)d_in[12];
    const float* Wv      = (const float*)d_in[13];
    const float* bv      = (const float*)d_in[14];
    float* out = (float*)d_out;

    static int s_attr_done = 0;
    if (!s_attr_done) {
        cudaFuncSetAttribute(k_gemm0_mma,
                             cudaFuncAttributeMaxDynamicSharedMemorySize, SMEM_DYN);
        cudaFuncSetAttribute(k_h0row_mma,
                             cudaFuncAttributeMaxDynamicSharedMemorySize, H0_SMEM);
        cudaFuncSetAttribute(k_gemm1_mma,
                             cudaFuncAttributeMaxDynamicSharedMemorySize, G1_SMEM);
        s_attr_done = 1;
    }

    k_xsplit<<<(M_ROWS * OBS) / (16 * 256), 256>>>(flat, nodes, num_nodes);
    k_wsplit<<<dim3(32, 16), dim3(32, 8)>>>(W0_rel, W0_root);
    k_w1split<<<256, 256>>>(W1_rel, W1_root);
    k_gemm0_mma<<<dim3(4, 256), 256, SMEM_DYN>>>();
    k_h0row_mma<<<BB, 256, H0_SMEM>>>(adj, num_nodes, b0);
    k_gemm1_mma<<<dim3(8, 2), 256, G1_SMEM>>>(b1);
    k_out<<<BB, 256>>>(Wl, bl, Wv, bv, out, out_size);
}

// round 17
// speedup vs baseline: 1.0146x; 1.0146x over previous
#include <cuda_runtime.h>
#include <cuda_fp16.h>
#include <cstdint>

#define GS 128
#define OBS 1024
#define HH 256
#define OUTD 1024
#define NO 18
#define BB 256
#define M_ROWS (BB * GS)   // 32768

// ---------------- scratch (device globals: no allocation allowed) -------------
__device__ __half g_Yh16[(size_t)M_ROWS * 256];  // rel half of Y, fp16
__device__ __half g_Yr16[(size_t)M_ROWS * 256];  // root half of Y, fp16
__device__ __half g_rh16[BB * 512];              // [r1 | h0_n] per batch, fp16
__device__ float g_no[BB * OUTD];                // node_out per batch
__device__ __half g_Xf[(size_t)M_ROWS * OBS];    // gathered X, fp16
__device__ __half g_Wf[512 * 1024];              // Wt[n][k] fp16 (layer 0)
__device__ __half g_W1f[512 * 1024];             // W1 concat [k][n] fp16 (layer 1)

// ---------------- helpers -----------------------------------------------------
__device__ __forceinline__ unsigned su32(const void* p) {
    return (unsigned)__cvta_generic_to_shared(p);
}
__device__ __forceinline__ unsigned pckh(float a, float b) {
    return (unsigned)__half_as_ushort(__float2half_rn(a))
         | ((unsigned)__half_as_ushort(__float2half_rn(b)) << 16);
}
#define STS8(addr, v) \
    asm volatile("st.shared.v2.u32 [%0], {%1, %2};" :: "r"(addr), "r"((v).x), "r"((v).y))
#define CPASYNC16(saddr, gptr) \
    asm volatile("cp.async.cg.shared.global [%0], [%1], 16;" \
                 :: "r"(saddr), "l"(gptr))
#define CPCOMMIT() asm volatile("cp.async.commit_group;")
#define CPWAIT1()  asm volatile("cp.async.wait_group 1;")
#define CPWAIT0()  asm volatile("cp.async.wait_group 0;")
#define LDSM4(r0, r1, r2, r3, a) \
    asm volatile("ldmatrix.sync.aligned.m8n8.x4.shared.b16 {%0,%1,%2,%3}, [%4];" \
                 : "=r"(r0), "=r"(r1), "=r"(r2), "=r"(r3) : "r"(a))
#define LDSM4T(r0, r1, r2, r3, a) \
    asm volatile("ldmatrix.sync.aligned.m8n8.x4.trans.shared.b16 {%0,%1,%2,%3}, [%4];" \
                 : "=r"(r0), "=r"(r1), "=r"(r2), "=r"(r3) : "r"(a))

__device__ __forceinline__ void mma_f16(float* c, const unsigned* a, const unsigned* b) {
    asm volatile(
        "mma.sync.aligned.m16n8k16.row.col.f32.f16.f16.f32 "
        "{%0,%1,%2,%3}, {%4,%5,%6,%7}, {%8,%9}, {%0,%1,%2,%3};"
        : "+f"(c[0]), "+f"(c[1]), "+f"(c[2]), "+f"(c[3])
        : "r"(a[0]), "r"(a[1]), "r"(a[2]), "r"(a[3]), "r"(b[0]), "r"(b[1]));
}

// ---------------- kernel 0: gather X rows + fp16 convert ----------------------
__global__ __launch_bounds__(256) void k_xsplit(const float* __restrict__ flat,
                                                const float* __restrict__ nodes,
                                                const int* __restrict__ num_nodes)
{
    int gid = blockIdx.x * 256 + threadIdx.x;
    int row = gid >> 6;
    int c0 = (gid & 63) * 16;
    int b = row >> 7, j = row & 127;
    const float* src = (j == num_nodes[b]) ? (flat + (size_t)b * OBS)
                                           : (nodes + (size_t)row * OBS);
    __half* dh = g_Xf + (size_t)row * OBS + c0;
#pragma unroll
    for (int i = 0; i < 4; ++i) {
        float4 v = *(const float4*)(src + c0 + i * 4);
        *(uint2*)(dh + i * 4) = make_uint2(pckh(v.x, v.y), pckh(v.z, v.w));
    }
}

// ---------------- kernel 0b: transpose + fp16 convert of [W0_rel|W0_root] -----
__global__ void k_wsplit(const float* __restrict__ W0_rel,
                         const float* __restrict__ W0_root)
{
    __shared__ float tile[32][33];
    int kb = blockIdx.x * 32, nb = blockIdx.y * 32;
    int tx = threadIdx.x, ty = threadIdx.y;  // (32, 8)
#pragma unroll
    for (int j = 0; j < 32; j += 8) {
        int k = kb + ty + j, n = nb + tx;
        float v = (n < 256) ? W0_rel[(size_t)k * 256 + n]
                            : W0_root[(size_t)k * 256 + (n - 256)];
        tile[ty + j][tx] = v;
    }
    __syncthreads();
#pragma unroll
    for (int j = 0; j < 32; j += 8) {
        int n = nb + ty + j, k = kb + tx;
        g_Wf[(size_t)n * 1024 + k] = __float2half_rn(tile[tx][ty + j]);
    }
}

// ---------------- kernel 0c: fp16 convert of W1 concat [k][n] -----------------
__global__ __launch_bounds__(256) void k_w1split(const float* __restrict__ W1_rel,
                                                 const float* __restrict__ W1_root)
{
    int gid = blockIdx.x * 256 + threadIdx.x;   // 8 halves each
    int k = gid >> 7;                           // 0..511
    int n = (gid & 127) * 8;
    const float* src = (k < 256) ? (W1_rel + (size_t)k * 1024 + n)
                                 : (W1_root + (size_t)(k - 256) * 1024 + n);
    float4 v0 = *(const float4*)(src);
    float4 v1 = *(const float4*)(src + 4);
    *(uint4*)(g_W1f + (size_t)k * 1024 + n) =
        make_uint4(pckh(v0.x, v0.y), pckh(v0.z, v0.w),
                   pckh(v1.x, v1.y), pckh(v1.z, v1.w));
}

// ---------------- kernel 1: Y = Xf @ Wf^T, cp.async 2-stage, single product ---
#define STAGE_BYTES 32768
#define SMEM_DYN (2 * STAGE_BYTES)     // 65536 -> 2 CTAs/SM

__global__ __launch_bounds__(256, 2) void k_gemm0_mma()
{
    extern __shared__ char dynsmem[];
    unsigned sm = su32(dynsmem);
    int tid = threadIdx.x, lane = tid & 31, wid = tid >> 5;
    int wm = wid >> 2, wn = wid & 3;               // warp tile: 64m x 32n
    int m0 = blockIdx.y * 128, n0 = blockIdx.x * 128;

    int cb = tid & 7;
    int r_lo = tid >> 3;
    unsigned swo = (unsigned)((cb ^ (r_lo & 7)) << 4);

    int l7 = lane & 7;
    unsigned a_row = (unsigned)(wm * 64 + (lane & 15)) * 128;
    unsigned a_cbx = (unsigned)(lane >> 4);
    unsigned b_row = (unsigned)(wn * 32 + l7) * 128;
    unsigned b_cbx = (unsigned)((lane >> 3) & 1);
    unsigned b_nt4 = (unsigned)((lane >> 4) & 1) * 1024;

    float acc[4][4][4];
#pragma unroll
    for (int mt = 0; mt < 4; ++mt)
#pragma unroll
        for (int nt = 0; nt < 4; ++nt)
#pragma unroll
            for (int r = 0; r < 4; ++r) acc[mt][nt][r] = 0.f;

#define ISSUE(cc)                                                              \
    {                                                                          \
        unsigned sb = sm + ((cc) & 1) * STAGE_BYTES;                           \
        int kt = (cc) * 64;                                                    \
        _Pragma("unroll")                                                      \
        for (int i = 0; i < 4; ++i) {                                          \
            int r = i * 32 + r_lo;                                             \
            unsigned so = (unsigned)(r * 128) + swo;                           \
            size_t goA = (size_t)(m0 + r) * 1024 + kt + cb * 8;                \
            size_t goB = (size_t)(n0 + r) * 1024 + kt + cb * 8;                \
            CPASYNC16(sb + so,         g_Xf + goA);                            \
            CPASYNC16(sb + 16384 + so, g_Wf + goB);                            \
        }                                                                      \
        CPCOMMIT();                                                            \
    }

    ISSUE(0);

    for (int c = 0; c < 16; ++c) {
        if (c + 1 < 16) { ISSUE(c + 1); CPWAIT1(); }
        else            { CPWAIT0(); }
        __syncthreads();
        unsigned base = sm + (c & 1) * STAGE_BYTES;
#pragma unroll
        for (int s = 0; s < 4; ++s) {
            unsigned a[4][4], bf[2][4];
            unsigned asw = (unsigned)((((unsigned)(s * 2) + a_cbx) ^ (unsigned)l7) << 4);
            unsigned bsw = (unsigned)((((unsigned)(s * 2) + b_cbx) ^ (unsigned)l7) << 4);
#pragma unroll
            for (int mt = 0; mt < 4; ++mt) {
                unsigned aaddr = base + a_row + mt * 2048 + asw;
                LDSM4(a[mt][0], a[mt][1], a[mt][2], a[mt][3], aaddr);
            }
#pragma unroll
            for (int p = 0; p < 2; ++p) {
                unsigned baddr = base + 16384 + b_row + p * 2048 + b_nt4 + bsw;
                LDSM4(bf[p][0], bf[p][1], bf[p][2], bf[p][3], baddr);
            }
#pragma unroll
            for (int mt = 0; mt < 4; ++mt)
#pragma unroll
                for (int p = 0; p < 2; ++p) {
                    mma_f16(acc[mt][p * 2 + 0], a[mt], bf[p] + 0);
                    mma_f16(acc[mt][p * 2 + 1], a[mt], bf[p] + 2);
                }
        }
        __syncthreads();
    }

    // epilogue: both halves stored fp16 (rel -> g_Yh16, root -> g_Yr16)
    bool isrel = (n0 < 256);
#pragma unroll
    for (int mt = 0; mt < 4; ++mt) {
        int m = m0 + wm * 64 + mt * 16 + (lane >> 2);
#pragma unroll
        for (int nt = 0; nt < 4; ++nt) {
            int n = n0 + wn * 32 + nt * 8 + (lane & 3) * 2;
            __half* dst0 = isrel ? (g_Yh16 + (size_t)m * 256 + n)
                                 : (g_Yr16 + (size_t)m * 256 + (n - 256));
            __half* dst1 = isrel ? (g_Yh16 + (size_t)(m + 8) * 256 + n)
                                 : (g_Yr16 + (size_t)(m + 8) * 256 + (n - 256));
            *(unsigned*)dst0 = pckh(acc[mt][nt][0], acc[mt][nt][1]);
            *(unsigned*)dst1 = pckh(acc[mt][nt][2], acc[mt][nt][3]);
        }
    }
#undef ISSUE
}

// ---------------- kernel 2: one CTA per batch, fused h0 + masked reduce -------
// smem: At 32K | Yh0 32K | Yh1 32K | bitw 2K | red 2K | sn
#define AT_OFF   0
#define YH0_OFF  32768
#define YH1_OFF  65536
#define BITW_OFF 98304
#define RED_OFF  100352
#define SN_OFF   102400
#define H0_SMEM  102416

__global__ __launch_bounds__(256, 2) void k_h0row_mma(const int* __restrict__ adj,
                                                      const int* __restrict__ num_nodes,
                                                      const float* __restrict__ b0)
{
    extern __shared__ char dynsmem[];
    unsigned sm = su32(dynsmem);
    unsigned At = sm + AT_OFF;
    unsigned YhBuf[2] = {sm + YH0_OFF, sm + YH1_OFF};
    unsigned* bitw = (unsigned*)(dynsmem + BITW_OFF);   // [128][4]
    float* red = (float*)(dynsmem + RED_OFF);           // [4][128]
    int* snp = (int*)(dynsmem + SN_OFF);
    int tid = threadIdx.x, lane = tid & 31, wid = tid >> 5;
    int wm = wid >> 1, wn = wid & 1;       // warp tile: 32 rows x 64 cols
    int b = blockIdx.x;

    // ---- prefetch both Yrel ch-tiles via cp.async ----
#pragma unroll
    for (int ch = 0; ch < 2; ++ch) {
#pragma unroll
        for (int it = 0; it < 8; ++it) {
            int s = it * 256 + tid;
            int j = s >> 4, g = s & 15;
            unsigned so = (unsigned)(j * 256 + ((g ^ (j & 7)) << 4));
            CPASYNC16(YhBuf[ch] + so,
                      g_Yh16 + (size_t)(b * 128 + j) * 256 + ch * 128 + g * 8);
        }
        CPCOMMIT();
    }

    // ---- adjacency bitset: int4 loads + shuffle-assembled masks ----
    // quad q = grp*1024 + it*256 + tid covers row j = q>>5, cols 4p..4p+3 (p=q&31)
    const int4* adj4 = (const int4*)(adj + (size_t)b * GS * GS);
#pragma unroll
    for (int grp = 0; grp < 4; ++grp) {
        int4 va[4];
#pragma unroll
        for (int it = 0; it < 4; ++it)
            va[it] = adj4[grp * 1024 + it * 256 + tid];
#pragma unroll
        for (int it = 0; it < 4; ++it) {
            int q = grp * 1024 + it * 256 + tid;
            int p = q & 31;
            unsigned nib = (unsigned)(va[it].x != 0)
                         | ((unsigned)(va[it].y != 0) << 1)
                         | ((unsigned)(va[it].z != 0) << 2)
                         | ((unsigned)(va[it].w != 0) << 3);
            unsigned contrib = nib << ((p & 7) * 4);
            contrib |= __shfl_xor_sync(0xffffffffu, contrib, 1);
            contrib |= __shfl_xor_sync(0xffffffffu, contrib, 2);
            contrib |= __shfl_xor_sync(0xffffffffu, contrib, 4);
            if ((p & 7) == 0) bitw[(q >> 5) * 4 + (p >> 3)] = contrib;
        }
    }
    __syncthreads();
    if (tid == 0) {
        int n = num_nodes[b];
        *snp = n;
        bitw[n * 4 + (n >> 5)] |= 1u << (n & 31);
        if (n > 0) {
            bitw[n * 4 + ((n - 1) >> 5)] |= 1u << ((n - 1) & 31);
            bitw[(n - 1) * 4 + (n >> 5)] |= 1u << (n & 31);
        }
    }
    __syncthreads();

    // ---- expand A^T[i][j] into fp16 0/1, swizzled ----
#pragma unroll
    for (int it = 0; it < 16; ++it) {
        int s = it * 256 + tid;
        int i = s >> 5, j0 = (s & 31) * 4;
        unsigned w = (unsigned)(i >> 5), bi = (unsigned)(i & 31);
        const unsigned ONE = 0x3C00u;
        unsigned e0 = (bitw[(j0 + 0) * 4 + w] >> bi) & 1u;
        unsigned e1 = (bitw[(j0 + 1) * 4 + w] >> bi) & 1u;
        unsigned e2 = (bitw[(j0 + 2) * 4 + w] >> bi) & 1u;
        unsigned e3 = (bitw[(j0 + 3) * 4 + w] >> bi) & 1u;
        unsigned p0 = (e0 * ONE) | ((e1 * ONE) << 16);
        unsigned p1 = (e2 * ONE) | ((e3 * ONE) << 16);
        unsigned so = (unsigned)(i * 256 + (((j0 >> 3) ^ (i & 7)) << 4) + (j0 & 7) * 2);
        STS8(At + so, make_uint2(p0, p1));
    }

    int n = *snp;
    unsigned nw = (unsigned)(n >> 5), nbit = 1u << (n & 31);

#pragma unroll
    for (int ch = 0; ch < 2; ++ch) {
        if (ch == 0) CPWAIT1(); else CPWAIT0();
        __syncthreads();
        unsigned Yh = YhBuf[ch];

        float acc[2][8][4];
#pragma unroll
        for (int mt = 0; mt < 2; ++mt)
#pragma unroll
            for (int nt = 0; nt < 8; ++nt)
#pragma unroll
                for (int r = 0; r < 4; ++r) acc[mt][nt][r] = 0.f;

        for (int s = 0; s < 8; ++s) {
            unsigned af[2][4];
#pragma unroll
            for (int mt = 0; mt < 2; ++mt) {
                int r = wm * 32 + mt * 16 + (lane & 15);
                unsigned ad = At + (unsigned)(r * 256)
                            + ((((unsigned)(s * 2 + (lane >> 4))) ^ (unsigned)(r & 7)) << 4);
                LDSM4(af[mt][0], af[mt][1], af[mt][2], af[mt][3], ad);
            }
            int jj = s * 16 + (lane & 15);
            unsigned brow = (unsigned)(jj * 256);
            unsigned jx = (unsigned)(jj & 7);
#pragma unroll
            for (int ntp = 0; ntp < 4; ++ntp) {
                unsigned colblk = (unsigned)(wn * 8 + ntp * 2) + (unsigned)(lane >> 4);
                unsigned bd = brow + ((colblk ^ jx) << 4);
                unsigned bfr[4];
                LDSM4T(bfr[0], bfr[1], bfr[2], bfr[3], Yh + bd);
#pragma unroll
                for (int mt = 0; mt < 2; ++mt) {
                    mma_f16(acc[mt][ntp * 2 + 0], af[mt], bfr + 0);
                    mma_f16(acc[mt][ntp * 2 + 1], af[mt], bfr + 2);
                }
            }
        }

        // ---- epilogue: relu(+root(fp16)+bias), masked r1, h0_n -> fp16 ----
        float r1p[8][2];
#pragma unroll
        for (int nt = 0; nt < 8; ++nt) { r1p[nt][0] = 0.f; r1p[nt][1] = 0.f; }

#pragma unroll
        for (int mt = 0; mt < 2; ++mt)
#pragma unroll
            for (int hr = 0; hr < 2; ++hr) {
                int i = wm * 32 + mt * 16 + (lane >> 2) + hr * 8;
                bool msk = (bitw[i * 4 + nw] & nbit) != 0;
                const __half* rootrow = g_Yr16 + (size_t)(b * 128 + i) * 256 + ch * 128;
#pragma unroll
                for (int nt = 0; nt < 8; ++nt) {
                    int cl = wn * 64 + nt * 8 + (lane & 3) * 2;
                    float2 root = __half22float2(*(const __half2*)(rootrow + cl));
                    float2 bbv = *(const float2*)(b0 + ch * 128 + cl);
                    float o0 = fmaxf(acc[mt][nt][hr * 2 + 0] + root.x + bbv.x, 0.f);
                    float o1 = fmaxf(acc[mt][nt][hr * 2 + 1] + root.y + bbv.y, 0.f);
                    if (msk) { r1p[nt][0] += o0; r1p[nt][1] += o1; }
                    if (i == n)
                        *(unsigned*)(g_rh16 + b * 512 + 256 + ch * 128 + cl) =
                            pckh(o0, o1);
                }
            }

#pragma unroll
        for (int nt = 0; nt < 8; ++nt)
#pragma unroll
            for (int t = 0; t < 2; ++t) {
                float v = r1p[nt][t];
                v += __shfl_xor_sync(0xffffffffu, v, 4);
                v += __shfl_xor_sync(0xffffffffu, v, 8);
                v += __shfl_xor_sync(0xffffffffu, v, 16);
                r1p[nt][t] = v;
            }
        if ((lane >> 2) == 0) {
#pragma unroll
            for (int nt = 0; nt < 8; ++nt) {
                red[wm * 128 + wn * 64 + nt * 8 + (lane & 3) * 2 + 0] = r1p[nt][0];
                red[wm * 128 + wn * 64 + nt * 8 + (lane & 3) * 2 + 1] = r1p[nt][1];
            }
        }
        __syncthreads();
        if (tid < 128) {
            float ssum = red[tid] + red[128 + tid] + red[256 + tid] + red[384 + tid];
            g_rh16[b * 512 + ch * 128 + tid] = __float2half_rn(ssum);
        }
        __syncthreads();
    }
}

// ---------------- kernel 4: node_out = relu(rh16 @ W1f + b1) via fp16 mma -----
#define G1_SMEM 65536

__global__ __launch_bounds__(256, 2) void k_gemm1_mma(const float* __restrict__ b1)
{
    extern __shared__ char dynsmem[];
    unsigned sm = su32(dynsmem);
    unsigned Ab0 = sm, Ab1 = sm + 16384;
    unsigned Bb0 = sm + 32768, Bb1 = sm + 49152;
    int tid = threadIdx.x, lane = tid & 31, wid = tid >> 5;
    int wm = wid >> 2, wn = wid & 3;               // warp tile: 64m x 32n
    int m0 = blockIdx.y * 128, n0 = blockIdx.x * 128;

    int cbA = tid & 7, rA_lo = tid >> 3;
    unsigned swoA = (unsigned)((cbA ^ (rA_lo & 7)) << 4);
    int gB = tid & 15, rB_lo = tid >> 4;

    int l7 = lane & 7;
    unsigned a_row = (unsigned)(wm * 64 + (lane & 15)) * 128;
    unsigned a_cbx = (unsigned)(lane >> 4);

    float acc[4][4][4];
#pragma unroll
    for (int mt = 0; mt < 4; ++mt)
#pragma unroll
        for (int nt = 0; nt < 4; ++nt)
#pragma unroll
            for (int r = 0; r < 4; ++r) acc[mt][nt][r] = 0.f;

#define ISSUE1(cc)                                                             \
    {                                                                          \
        unsigned Ab = ((cc) & 1) ? Ab1 : Ab0;                                  \
        unsigned Bb = ((cc) & 1) ? Bb1 : Bb0;                                  \
        int kt = (cc) * 64;                                                    \
        _Pragma("unroll")                                                      \
        for (int i = 0; i < 4; ++i) {                                          \
            int rA = i * 32 + rA_lo;                                           \
            CPASYNC16(Ab + (unsigned)(rA * 128) + swoA,                        \
                      g_rh16 + (size_t)(m0 + rA) * 512 + kt + cbA * 8);        \
            int rB = i * 16 + rB_lo;                                           \
            unsigned soB = (unsigned)(rB * 256 + ((gB ^ (rB & 7)) << 4));      \
            CPASYNC16(Bb + soB,                                                \
                      g_W1f + (size_t)(kt + rB) * 1024 + n0 + gB * 8);         \
        }                                                                      \
        CPCOMMIT();                                                            \
    }

    ISSUE1(0);

    for (int c = 0; c < 8; ++c) {
        if (c + 1 < 8) { ISSUE1(c + 1); CPWAIT1(); }
        else           { CPWAIT0(); }
        __syncthreads();
        unsigned Ab = (c & 1) ? Ab1 : Ab0;
        unsigned Bb = (c & 1) ? Bb1 : Bb0;
#pragma unroll
        for (int s = 0; s < 4; ++s) {
            unsigned a[4][4];
            unsigned asw = (unsigned)((((unsigned)(s * 2) + a_cbx) ^ (unsigned)l7) << 4);
#pragma unroll
            for (int mt = 0; mt < 4; ++mt)
                LDSM4(a[mt][0], a[mt][1], a[mt][2], a[mt][3],
                      Ab + a_row + mt * 2048 + asw);
            int jj = s * 16 + (lane & 15);
            unsigned brow = (unsigned)(jj * 256);
            unsigned jx = (unsigned)(jj & 7);
#pragma unroll
            for (int ntp = 0; ntp < 2; ++ntp) {
                unsigned colblk = (unsigned)(wn * 4 + ntp * 2) + (unsigned)(lane >> 4);
                unsigned bd = brow + ((colblk ^ jx) << 4);
                unsigned bfr[4];
                LDSM4T(bfr[0], bfr[1], bfr[2], bfr[3], Bb + bd);
#pragma unroll
                for (int mt = 0; mt < 4; ++mt) {
                    mma_f16(acc[mt][ntp * 2 + 0], a[mt], bfr + 0);
                    mma_f16(acc[mt][ntp * 2 + 1], a[mt], bfr + 2);
                }
            }
        }
        __syncthreads();
    }

    // epilogue: +b1, relu -> g_no fp32
#pragma unroll
    for (int mt = 0; mt < 4; ++mt) {
        int m = m0 + wm * 64 + mt * 16 + (lane >> 2);
#pragma unroll
        for (int nt = 0; nt < 4; ++nt) {
            int n = n0 + wn * 32 + nt * 8 + (lane & 3) * 2;
            float2 bb = *(const float2*)(b1 + n);
            *(float2*)(g_no + (size_t)m * 1024 + n) =
                make_float2(fmaxf(acc[mt][nt][0] + bb.x, 0.f),
                            fmaxf(acc[mt][nt][1] + bb.y, 0.f));
            *(float2*)(g_no + (size_t)(m + 8) * 1024 + n) =
                make_float2(fmaxf(acc[mt][nt][2] + bb.x, 0.f),
                            fmaxf(acc[mt][nt][3] + bb.y, 0.f));
        }
    }
#undef ISSUE1
}

// ---------------- kernel 5: logits + value -----------------------------------
__global__ __launch_bounds__(256) void k_out(const float* __restrict__ Wl,
                                             const float* __restrict__ bl,
                                             const float* __restrict__ Wv,
                                             const float* __restrict__ bv,
                                             float* __restrict__ out, int out_size)
{
    int b = blockIdx.x;
    int w = threadIdx.x >> 5, lane = threadIdx.x & 31;
    const float* nb = g_no + (size_t)b * 1024;
    for (int o = w; o < 19; o += 8) {
        float acc = 0.f;
        if (o < 18) {
            for (int i = lane; i < 1024; i += 32) acc += nb[i] * Wl[i * 18 + o];
        } else {
            for (int i = lane; i < 1024; i += 32) acc += nb[i] * Wv[i];
        }
#pragma unroll
        for (int s = 16; s; s >>= 1) acc += __shfl_down_sync(0xffffffffu, acc, s);
        if (lane == 0) {
            if (o < 18) {
                int idx = b * NO + o;
                if (idx < out_size) out[idx] = acc + bl[o];
            } else {
                int idx = BB * NO + b;
                if (idx < out_size) out[idx] = acc + bv[0];
            }
        }
    }
}

// ---------------- launch ------------------------------------------------------
extern "C" void kernel_launch(void* const* d_in, const int* in_sizes, int n_in,
                              void* d_out, int out_size)
{
    const float* flat      = (const float*)d_in[0];
    const float* nodes     = (const float*)d_in[1];
    const int*   num_nodes = (const int*)d_in[2];
    const int*   adj       = (const int*)d_in[3];
    // d_in[4] = seq_lens (unused)
    const float* W0_rel  = (const float*)d_in[5];
    const float* b0      = (const float*)d_in[6];
    const float* W0_root = (const float*)d_in[7];
    const float* W1_rel  = (const float*)d_in[8];
    const float* b1      = (const float*)d_in[9];
    const float* W1_root = (const float*)d_in[10];
    const float* Wl      = (const float*)d_in[11];
    const float* bl      = (const float*)d_in[12];
    const float* Wv      = (const float*)d_in[13];
    const float* bv      = (const float*)d_in[14];
    float* out = (float*)d_out;

    static int s_attr_done = 0;
    if (!s_attr_done) {
        cudaFuncSetAttribute(k_gemm0_mma,
                             cudaFuncAttributeMaxDynamicSharedMemorySize, SMEM_DYN);
        cudaFuncSetAttribute(k_h0row_mma,
                             cudaFuncAttributeMaxDynamicSharedMemorySize, H0_SMEM);
        cudaFuncSetAttribute(k_gemm1_mma,
                             cudaFuncAttributeMaxDynamicSharedMemorySize, G1_SMEM);
        s_attr_done = 1;
    }

    k_xsplit<<<(M_ROWS * OBS) / (16 * 256), 256>>>(flat, nodes, num_nodes);
    k_wsplit<<<dim3(32, 16), dim3(32, 8)>>>(W0_rel, W0_root);
    k_w1split<<<256, 256>>>(W1_rel, W1_root);
    k_gemm0_mma<<<dim3(4, 256), 256, SMEM_DYN>>>();
    k_h0row_mma<<<BB, 256, H0_SMEM>>>(adj, num_nodes, b0);
    k_gemm1_mma<<<dim3(8, 2), 256, G1_SMEM>>>(b1);
    k_out<<<BB, 256>>>(Wl, bl, Wv, bv, out, out_size);
}